// round 3
// baseline (speedup 1.0000x reference)
#include <cuda_runtime.h>

// BEVGenerator: B=32, N=131072 points, S=6 z-slices, 256x256 BEV images.
// Pipeline: memset out -> init minmax -> z min/max reduce -> scatter histogram
//           -> log1p + per-image minmax normalize.

namespace {
constexpr int B = 32;
constexpr int N = 131072;       // 2^17
constexpr int S = 6;
constexpr int H = 256;
constexpr int W = 256;
constexpr int RED_SPLIT = 16;   // blocks per batch in the reduce
constexpr int RED_CHUNK = N / RED_SPLIT;  // 8192
}

// Scratch (no allocations allowed): per-batch z min/max as order-preserving uints.
__device__ unsigned g_zmin_enc[B];
__device__ unsigned g_zmax_enc[B];

__device__ __forceinline__ unsigned enc_f(float f) {
    unsigned u = __float_as_uint(f);
    return (u & 0x80000000u) ? ~u : (u | 0x80000000u);
}
__device__ __forceinline__ float dec_f(unsigned e) {
    unsigned u = (e & 0x80000000u) ? (e ^ 0x80000000u) : ~e;
    return __uint_as_float(u);
}

__global__ void init_minmax_kernel() {
    int t = threadIdx.x;
    if (t < B) {
        g_zmin_enc[t] = 0xFFFFFFFFu;  // > enc(+inf): any real value wins
        g_zmax_enc[t] = 0u;           // < enc(-inf): any real value wins
    }
}

__global__ void reduce_minmax_kernel(const float* __restrict__ xyz) {
    int b = blockIdx.x / RED_SPLIT;
    int part = blockIdx.x % RED_SPLIT;
    const float* bp = xyz + (size_t)b * N * 3;
    float mn = __int_as_float(0x7f800000);   // +inf
    float mx = -mn;
    int j0 = part * RED_CHUNK;
    for (int j = j0 + threadIdx.x; j < j0 + RED_CHUNK; j += blockDim.x) {
        float z = __ldg(bp + (size_t)j * 3 + 2);
        mn = fminf(mn, z);
        mx = fmaxf(mx, z);
    }
    // warp reduce
    #pragma unroll
    for (int o = 16; o; o >>= 1) {
        mn = fminf(mn, __shfl_down_sync(0xffffffffu, mn, o));
        mx = fmaxf(mx, __shfl_down_sync(0xffffffffu, mx, o));
    }
    __shared__ float smn[8], smx[8];
    int w = threadIdx.x >> 5;
    if ((threadIdx.x & 31) == 0) { smn[w] = mn; smx[w] = mx; }
    __syncthreads();
    if (threadIdx.x == 0) {
        #pragma unroll
        for (int i = 1; i < 8; i++) { mn = fminf(mn, smn[i]); mx = fmaxf(mx, smx[i]); }
        atomicMin(&g_zmin_enc[b], enc_f(mn));
        atomicMax(&g_zmax_enc[b], enc_f(mx));
    }
}

__global__ void hist_kernel(const float* __restrict__ xyz, float* __restrict__ out) {
    int idx = blockIdx.x * blockDim.x + threadIdx.x;   // point id, < B*N
    int b = idx >> 17;                                  // N = 2^17
    const float* p = xyz + (size_t)idx * 3;
    float x = p[0];
    float y = p[1];
    float z = p[2];

    // Pixel coords: IEEE ops, no contraction (must bit-match XLA for the int cast).
    float gx = __fmul_rn(__fdiv_rn(__fadd_rn(x, 1.0f), 2.000001f), 255.0f);
    float gy = __fmul_rn(__fdiv_rn(__fadd_rn(y, 1.0f), 2.000001f), 255.0f);
    bool valid = (gy >= 0.0f) & (gy < 256.0f) & (gx >= 0.0f) & (gx < 256.0f);

    float zmn = dec_f(g_zmin_enc[b]);
    float rng = __fsub_rn(dec_f(g_zmax_enc[b]), zmn);

    // edges[k] = zmn + rng * (k * (1/6)), matching linspace's iota*step, un-fused.
    const float delta = 1.0f / 6.0f;
    int s = -1;
    float e_prev = zmn;  // alpha = 0
    #pragma unroll
    for (int k = 0; k < S; k++) {
        float alpha = __fmul_rn((float)(k + 1), delta);
        float e_next = __fadd_rn(zmn, __fmul_rn(rng, alpha));
        if ((z >= e_prev) & (z < e_next)) s = k;
        e_prev = e_next;
    }

    if (valid & (s >= 0)) {
        int iy = (int)gy;   // trunc == floor (nonneg), in range by `valid`
        int ix = (int)gx;
        int bin = ((b * S + s) * H + iy) * W + ix;
        atomicAdd(out + bin, 1.0f);
    }
}

// One block per (b, s) image. log1p is strictly monotone, so min/max over
// log1p(counts) == log1p(min/max counts): reduce on raw counts, then a single
// transform+normalize pass (second read hits L2: 256 KB/block working set).
__global__ void finalize_kernel(float* __restrict__ out) {
    float* p = out + (size_t)blockIdx.x * H * W;
    float cmn = __int_as_float(0x7f800000);
    float cmx = -cmn;
    for (int i = threadIdx.x; i < H * W; i += blockDim.x) {
        float c = p[i];
        cmn = fminf(cmn, c);
        cmx = fmaxf(cmx, c);
    }
    __shared__ float smn[256], smx[256];
    smn[threadIdx.x] = cmn;
    smx[threadIdx.x] = cmx;
    __syncthreads();
    #pragma unroll
    for (int o = 128; o; o >>= 1) {
        if (threadIdx.x < o) {
            smn[threadIdx.x] = fminf(smn[threadIdx.x], smn[threadIdx.x + o]);
            smx[threadIdx.x] = fmaxf(smx[threadIdx.x], smx[threadIdx.x + o]);
        }
        __syncthreads();
    }
    float mn = log1pf(smn[0]);
    float mx = log1pf(smx[0]);
    float inv = 1.0f / (mx - mn + 1e-6f);
    for (int i = threadIdx.x; i < H * W; i += blockDim.x) {
        p[i] = (log1pf(p[i]) - mn) * inv;
    }
}

extern "C" void kernel_launch(void* const* d_in, const int* in_sizes, int n_in,
                              void* d_out, int out_size) {
    const float* xyz = (const float*)d_in[0];
    float* out = (float*)d_out;
    (void)in_sizes; (void)n_in;

    cudaMemsetAsync(out, 0, (size_t)out_size * sizeof(float));
    init_minmax_kernel<<<1, 32>>>();
    reduce_minmax_kernel<<<B * RED_SPLIT, 256>>>(xyz);
    hist_kernel<<<(B * N) / 256, 256>>>(xyz, out);
    finalize_kernel<<<B * S, 256>>>(out);
}

// round 4
// speedup vs baseline: 1.9248x; 1.9248x over previous
#include <cuda_runtime.h>

// BEVGenerator: B=32, N=131072 points, S=6 z-slices, 256x256 BEV images.
// Pipeline: memset out -> init scratch -> z min/max reduce -> scatter histogram
//           -> per-image count min/max (phase A) -> log1p+normalize (phase B).

namespace {
constexpr int B = 32;
constexpr int N = 131072;       // 2^17
constexpr int S = 6;
constexpr int H = 256;
constexpr int W = 256;
constexpr int NIMG = B * S;             // 192
constexpr int IMG_ELEMS = H * W;        // 65536
constexpr int RED_SPLIT = 16;           // blocks per batch in the z-reduce
constexpr int RED_CHUNK = N / RED_SPLIT;
constexpr int MM_SPLIT = 8;             // blocks per image in count min/max
constexpr int MM_V4_PER_BLOCK = IMG_ELEMS / 4 / MM_SPLIT;  // 2048 float4
}

// Scratch (no allocations allowed).
__device__ unsigned g_zmin_enc[B];
__device__ unsigned g_zmax_enc[B];
__device__ unsigned g_img_min[NIMG];   // raw float bits (counts >= 0: uint order == float order)
__device__ unsigned g_img_max[NIMG];

__device__ __forceinline__ unsigned enc_f(float f) {
    unsigned u = __float_as_uint(f);
    return (u & 0x80000000u) ? ~u : (u | 0x80000000u);
}
__device__ __forceinline__ float dec_f(unsigned e) {
    unsigned u = (e & 0x80000000u) ? (e ^ 0x80000000u) : ~e;
    return __uint_as_float(u);
}

__global__ void init_scratch_kernel() {
    int t = threadIdx.x;
    if (t < B) {
        g_zmin_enc[t] = 0xFFFFFFFFu;
        g_zmax_enc[t] = 0u;
    }
    if (t < NIMG) {
        g_img_min[t] = 0x7f800000u;  // +inf bits
        g_img_max[t] = 0u;           // 0.0f bits (counts >= 0)
    }
}

__global__ void reduce_minmax_kernel(const float* __restrict__ xyz) {
    int b = blockIdx.x / RED_SPLIT;
    int part = blockIdx.x % RED_SPLIT;
    const float* bp = xyz + (size_t)b * N * 3;
    float mn = __int_as_float(0x7f800000);
    float mx = -mn;
    int j0 = part * RED_CHUNK;
    for (int j = j0 + threadIdx.x; j < j0 + RED_CHUNK; j += blockDim.x) {
        float z = __ldg(bp + (size_t)j * 3 + 2);
        mn = fminf(mn, z);
        mx = fmaxf(mx, z);
    }
    #pragma unroll
    for (int o = 16; o; o >>= 1) {
        mn = fminf(mn, __shfl_down_sync(0xffffffffu, mn, o));
        mx = fmaxf(mx, __shfl_down_sync(0xffffffffu, mx, o));
    }
    __shared__ float smn[8], smx[8];
    int w = threadIdx.x >> 5;
    if ((threadIdx.x & 31) == 0) { smn[w] = mn; smx[w] = mx; }
    __syncthreads();
    if (threadIdx.x == 0) {
        #pragma unroll
        for (int i = 1; i < 8; i++) { mn = fminf(mn, smn[i]); mx = fmaxf(mx, smx[i]); }
        atomicMin(&g_zmin_enc[b], enc_f(mn));
        atomicMax(&g_zmax_enc[b], enc_f(mx));
    }
}

__global__ void hist_kernel(const float* __restrict__ xyz, float* __restrict__ out) {
    int idx = blockIdx.x * blockDim.x + threadIdx.x;   // point id, < B*N
    int b = idx >> 17;                                  // N = 2^17
    const float* p = xyz + (size_t)idx * 3;
    float x = p[0];
    float y = p[1];
    float z = p[2];

    // Pixel coords: IEEE ops, no contraction (must bit-match XLA for the int cast).
    float gx = __fmul_rn(__fdiv_rn(__fadd_rn(x, 1.0f), 2.000001f), 255.0f);
    float gy = __fmul_rn(__fdiv_rn(__fadd_rn(y, 1.0f), 2.000001f), 255.0f);
    bool valid = (gy >= 0.0f) & (gy < 256.0f) & (gx >= 0.0f) & (gx < 256.0f);

    float zmn = dec_f(g_zmin_enc[b]);
    float rng = __fsub_rn(dec_f(g_zmax_enc[b]), zmn);

    // edges[k] = zmn + rng * (k * (1/6)), matching linspace's iota*step, un-fused.
    const float delta = 1.0f / 6.0f;
    int s = -1;
    float e_prev = zmn;
    #pragma unroll
    for (int k = 0; k < S; k++) {
        float alpha = __fmul_rn((float)(k + 1), delta);
        float e_next = __fadd_rn(zmn, __fmul_rn(rng, alpha));
        if ((z >= e_prev) & (z < e_next)) s = k;
        e_prev = e_next;
    }

    if (valid & (s >= 0)) {
        int iy = (int)gy;
        int ix = (int)gx;
        int bin = ((b * S + s) * H + iy) * W + ix;
        atomicAdd(out + bin, 1.0f);
    }
}

// Phase A: per-image count min/max. 8 blocks per image, float4 loads, 8-deep MLP.
// Counts are >= 0 so raw float bits compare correctly as unsigned.
__global__ void img_minmax_kernel(const float* __restrict__ out) {
    int img = blockIdx.x / MM_SPLIT;
    int part = blockIdx.x % MM_SPLIT;
    const float4* p4 = (const float4*)out + (size_t)img * (IMG_ELEMS / 4)
                       + (size_t)part * MM_V4_PER_BLOCK;
    float mn = __int_as_float(0x7f800000);
    float mx = 0.0f;
    #pragma unroll
    for (int j = 0; j < MM_V4_PER_BLOCK / 256; j++) {   // 8 iterations
        float4 v = __ldg(p4 + j * 256 + threadIdx.x);
        mn = fminf(fminf(fminf(mn, v.x), fminf(v.y, v.z)), v.w);
        mx = fmaxf(fmaxf(fmaxf(mx, v.x), fmaxf(v.y, v.z)), v.w);
    }
    #pragma unroll
    for (int o = 16; o; o >>= 1) {
        mn = fminf(mn, __shfl_down_sync(0xffffffffu, mn, o));
        mx = fmaxf(mx, __shfl_down_sync(0xffffffffu, mx, o));
    }
    __shared__ float smn[8], smx[8];
    int w = threadIdx.x >> 5;
    if ((threadIdx.x & 31) == 0) { smn[w] = mn; smx[w] = mx; }
    __syncthreads();
    if (threadIdx.x == 0) {
        #pragma unroll
        for (int i = 1; i < 8; i++) { mn = fminf(mn, smn[i]); mx = fmaxf(mx, smx[i]); }
        atomicMin(&g_img_min[img], __float_as_uint(mn));
        atomicMax(&g_img_max[img], __float_as_uint(mx));
    }
}

// Phase B: log1p + per-image minmax normalize, elementwise over float4.
// min/max(log1p(c)) == log1p(min/max c) since log1p is monotone.
__global__ void normalize_kernel(float* __restrict__ out) {
    int i4 = blockIdx.x * blockDim.x + threadIdx.x;     // float4 index
    int img = i4 >> 14;                                  // 16384 float4 per image
    float mn = log1pf(__uint_as_float(__ldg(&g_img_min[img])));
    float mx = log1pf(__uint_as_float(__ldg(&g_img_max[img])));
    float inv = 1.0f / (mx - mn + 1e-6f);
    float4* p4 = (float4*)out + i4;
    float4 v = *p4;
    v.x = (log1pf(v.x) - mn) * inv;
    v.y = (log1pf(v.y) - mn) * inv;
    v.z = (log1pf(v.z) - mn) * inv;
    v.w = (log1pf(v.w) - mn) * inv;
    *p4 = v;
}

extern "C" void kernel_launch(void* const* d_in, const int* in_sizes, int n_in,
                              void* d_out, int out_size) {
    const float* xyz = (const float*)d_in[0];
    float* out = (float*)d_out;
    (void)in_sizes; (void)n_in;

    cudaMemsetAsync(out, 0, (size_t)out_size * sizeof(float));
    init_scratch_kernel<<<1, 256>>>();
    reduce_minmax_kernel<<<B * RED_SPLIT, 256>>>(xyz);
    hist_kernel<<<(B * N) / 256, 256>>>(xyz, out);
    img_minmax_kernel<<<NIMG * MM_SPLIT, 256>>>(out);
    normalize_kernel<<<(NIMG * IMG_ELEMS / 4) / 256, 256>>>(out);
}

// round 5
// speedup vs baseline: 2.0769x; 1.0790x over previous
#include <cuda_runtime.h>

// BEVGenerator: B=32, N=131072 points, S=6 z-slices, 256x256 BEV images.
// Pipeline: memset out -> init scratch -> z min/max reduce -> scatter histogram
//           -> fused per-image minmax + log1p-normalize (one 8-CTA cluster per image,
//              counts held in registers across the cluster barrier).

namespace {
constexpr int B = 32;
constexpr int N = 131072;       // 2^17
constexpr int S = 6;
constexpr int H = 256;
constexpr int W = 256;
constexpr int NIMG = B * S;             // 192
constexpr int IMG_ELEMS = H * W;        // 65536
constexpr int RED_SPLIT = 16;           // blocks per batch in the z-reduce
constexpr int RED_CHUNK = N / RED_SPLIT;
constexpr int CL = 8;                   // blocks (cluster size) per image
constexpr int V4_PER_BLOCK = IMG_ELEMS / 4 / CL;   // 2048 float4 per block
constexpr int V4_PER_THREAD = V4_PER_BLOCK / 256;  // 8
}

// Scratch (no allocations allowed).
__device__ unsigned g_zmin_enc[B];
__device__ unsigned g_zmax_enc[B];
__device__ unsigned g_img_min[NIMG];   // raw float bits (counts >= 0: uint order == float order)
__device__ unsigned g_img_max[NIMG];

__device__ __forceinline__ unsigned enc_f(float f) {
    unsigned u = __float_as_uint(f);
    return (u & 0x80000000u) ? ~u : (u | 0x80000000u);
}
__device__ __forceinline__ float dec_f(unsigned e) {
    unsigned u = (e & 0x80000000u) ? (e ^ 0x80000000u) : ~e;
    return __uint_as_float(u);
}

__global__ void init_scratch_kernel() {
    int t = threadIdx.x;
    if (t < B) {
        g_zmin_enc[t] = 0xFFFFFFFFu;
        g_zmax_enc[t] = 0u;
    }
    if (t < NIMG) {
        g_img_min[t] = 0x7f800000u;  // +inf bits
        g_img_max[t] = 0u;           // 0.0f bits (counts >= 0)
    }
}

__global__ void reduce_minmax_kernel(const float* __restrict__ xyz) {
    int b = blockIdx.x / RED_SPLIT;
    int part = blockIdx.x % RED_SPLIT;
    const float* bp = xyz + (size_t)b * N * 3;
    float mn = __int_as_float(0x7f800000);
    float mx = -mn;
    int j0 = part * RED_CHUNK;
    for (int j = j0 + threadIdx.x; j < j0 + RED_CHUNK; j += blockDim.x) {
        float z = __ldg(bp + (size_t)j * 3 + 2);
        mn = fminf(mn, z);
        mx = fmaxf(mx, z);
    }
    #pragma unroll
    for (int o = 16; o; o >>= 1) {
        mn = fminf(mn, __shfl_down_sync(0xffffffffu, mn, o));
        mx = fmaxf(mx, __shfl_down_sync(0xffffffffu, mx, o));
    }
    __shared__ float smn[8], smx[8];
    int w = threadIdx.x >> 5;
    if ((threadIdx.x & 31) == 0) { smn[w] = mn; smx[w] = mx; }
    __syncthreads();
    if (threadIdx.x == 0) {
        #pragma unroll
        for (int i = 1; i < 8; i++) { mn = fminf(mn, smn[i]); mx = fmaxf(mx, smx[i]); }
        atomicMin(&g_zmin_enc[b], enc_f(mn));
        atomicMax(&g_zmax_enc[b], enc_f(mx));
    }
}

__global__ void hist_kernel(const float* __restrict__ xyz, float* __restrict__ out) {
    int idx = blockIdx.x * blockDim.x + threadIdx.x;   // point id, < B*N
    int b = idx >> 17;                                  // N = 2^17
    const float* p = xyz + (size_t)idx * 3;
    float x = p[0];
    float y = p[1];
    float z = p[2];

    // Pixel coords: IEEE ops, no contraction (must bit-match XLA for the int cast).
    float gx = __fmul_rn(__fdiv_rn(__fadd_rn(x, 1.0f), 2.000001f), 255.0f);
    float gy = __fmul_rn(__fdiv_rn(__fadd_rn(y, 1.0f), 2.000001f), 255.0f);
    bool valid = (gy >= 0.0f) & (gy < 256.0f) & (gx >= 0.0f) & (gx < 256.0f);

    float zmn = dec_f(g_zmin_enc[b]);
    float rng = __fsub_rn(dec_f(g_zmax_enc[b]), zmn);

    // edges[k] = zmn + rng * (k * (1/6)), matching linspace's iota*step, un-fused.
    const float delta = 1.0f / 6.0f;
    int s = -1;
    float e_prev = zmn;
    #pragma unroll
    for (int k = 0; k < S; k++) {
        float alpha = __fmul_rn((float)(k + 1), delta);
        float e_next = __fadd_rn(zmn, __fmul_rn(rng, alpha));
        if ((z >= e_prev) & (z < e_next)) s = k;
        e_prev = e_next;
    }

    if (valid & (s >= 0)) {
        int iy = (int)gy;
        int ix = (int)gx;
        int bin = ((b * S + s) * H + iy) * W + ix;
        atomicAdd(out + bin, 1.0f);
    }
}

// Fused finalize: one 8-CTA cluster per (b,s) image. Each block loads its
// 8192 counts into registers, reduces min/max, publishes via L2 atomics,
// cluster-syncs (flushes L1 so the readback sees all 8 blocks' atomics),
// then transforms the register-resident values and writes out.
// min/max(log1p(c)) == log1p(min/max c) since log1p is monotone.
__global__ void __cluster_dims__(CL, 1, 1) fused_finalize_kernel(float* __restrict__ out) {
    int img = blockIdx.x / CL;
    int part = blockIdx.x % CL;
    float4* p4 = (float4*)out + (size_t)img * (IMG_ELEMS / 4)
                 + (size_t)part * V4_PER_BLOCK;

    float4 vals[V4_PER_THREAD];
    float mn = __int_as_float(0x7f800000);
    float mx = 0.0f;
    #pragma unroll
    for (int j = 0; j < V4_PER_THREAD; j++) {
        vals[j] = p4[j * 256 + threadIdx.x];
        float4 v = vals[j];
        mn = fminf(fminf(fminf(mn, v.x), fminf(v.y, v.z)), v.w);
        mx = fmaxf(fmaxf(fmaxf(mx, v.x), fmaxf(v.y, v.z)), v.w);
    }
    #pragma unroll
    for (int o = 16; o; o >>= 1) {
        mn = fminf(mn, __shfl_down_sync(0xffffffffu, mn, o));
        mx = fmaxf(mx, __shfl_down_sync(0xffffffffu, mx, o));
    }
    __shared__ float smn[8], smx[8];
    int w = threadIdx.x >> 5;
    if ((threadIdx.x & 31) == 0) { smn[w] = mn; smx[w] = mx; }
    __syncthreads();
    if (threadIdx.x == 0) {
        #pragma unroll
        for (int i = 1; i < 8; i++) { mn = fminf(mn, smn[i]); mx = fmaxf(mx, smx[i]); }
        // counts >= 0 so raw float bits compare correctly as unsigned
        atomicMin(&g_img_min[img], __float_as_uint(mn));
        atomicMax(&g_img_max[img], __float_as_uint(mx));
    }

    // Cluster barrier: all 8 blocks' atomics land in L2 before any readback;
    // the implied L1 invalidate keeps the readback coherent.
    asm volatile("barrier.cluster.arrive.aligned;" ::: "memory");
    asm volatile("barrier.cluster.wait.aligned;" ::: "memory");

    float fmn = log1pf(__uint_as_float(g_img_min[img]));
    float fmx = log1pf(__uint_as_float(g_img_max[img]));
    float inv = 1.0f / (fmx - fmn + 1e-6f);

    #pragma unroll
    for (int j = 0; j < V4_PER_THREAD; j++) {
        float4 v = vals[j];
        v.x = (log1pf(v.x) - fmn) * inv;
        v.y = (log1pf(v.y) - fmn) * inv;
        v.z = (log1pf(v.z) - fmn) * inv;
        v.w = (log1pf(v.w) - fmn) * inv;
        p4[j * 256 + threadIdx.x] = v;
    }
}

extern "C" void kernel_launch(void* const* d_in, const int* in_sizes, int n_in,
                              void* d_out, int out_size) {
    const float* xyz = (const float*)d_in[0];
    float* out = (float*)d_out;
    (void)in_sizes; (void)n_in;

    cudaMemsetAsync(out, 0, (size_t)out_size * sizeof(float));
    init_scratch_kernel<<<1, 256>>>();
    reduce_minmax_kernel<<<B * RED_SPLIT, 256>>>(xyz);
    hist_kernel<<<(B * N) / 256, 256>>>(xyz, out);
    fused_finalize_kernel<<<NIMG * CL, 256>>>(out);
}